// round 5
// baseline (speedup 1.0000x reference)
#include <cuda_runtime.h>

#define LOG2E 1.4426950408889634f
#define EPS   1e-8f

__device__ float        g_partials[8192];
__device__ unsigned int g_done;   // zero-init; last block resets -> graph-replay safe

__device__ __forceinline__ float ex2a(float x) {
    float r; asm("ex2.approx.ftz.f32 %0, %1;" : "=f"(r) : "f"(x)); return r;
}
__device__ __forceinline__ float lg2a(float x) {
    float r; asm("lg2.approx.ftz.f32 %0, %1;" : "=f"(r) : "f"(x)); return r;
}

// Warp-per-row. 128 threads = 4 warps = 4 rows per block.
// Row data staged in smem with the first 64 entries mirrored past L so the
// cyclic partner index j = i + k never needs a wrap test (j <= L-1+63 < 192).
__global__ void __launch_bounds__(128) ndcg_kernel(
    const float* __restrict__ scores,
    const int*   __restrict__ relev,
    const int*   __restrict__ qlen,
    float*       __restrict__ out,
    int D, int B)
{
    const int lane = threadIdx.x & 31;
    const int wid  = threadIdx.x >> 5;
    const int row  = blockIdx.x * 4 + wid;

    __shared__ float2 s_sg[4][192];
    __shared__ int    s_cnt[4][8];
    __shared__ float  s_red[4];
    __shared__ int    s_last;

    if (row < B) {
        const int L     = qlen[row];           // warp-uniform
        const int halfm = (L - 1) >> 1;

        if (lane < 8) s_cnt[wid][lane] = 0;
        __syncwarp();

        // stage row: 4 docs per lane
        #pragma unroll
        for (int q = 0; q < 4; ++q) {
            const int   idx = lane + 32 * q;        // < 128 = D
            const float sv  = scores[row * D + idx];
            const int   rv  = relev[row * D + idx];
            const bool  v   = (idx < L);
            const float gv  = v ? (float)((1 << rv) - 1) : 0.0f;  // 2^rel - 1
            s_sg[wid][idx] = make_float2(sv, gv);
            if (v) atomicAdd(&s_cnt[wid][rv], 1);
        }
        __syncwarp();

        // mirror first 64 entries past L (only indices [L, L+halfm) are read,
        // halfm < 64, and sources t < halfm < L are valid docs)
        #pragma unroll
        for (int q = 0; q < 2; ++q) {
            const int t = lane + 32 * q;            // 0..63
            s_sg[wid][L + t] = s_sg[wid][t];
        }
        __syncwarp();

        // ---- pairwise sum over unordered valid pairs ----
        // pair {i,j}, a=|si-sj|: folded both-orders contribution
        //   -|gi-gj| * (a*log2e + 2*log2(1 + 2^{-a*log2e}))
        float num = 0.0f;
        const int nq = (L + 31) >> 5;               // warp-uniform
        for (int q = 0; q < nq; ++q) {
            const int i0 = lane + 32 * q;
            const float2  me   = s_sg[wid][i0 < 191 ? i0 : 191];
            const float2* base = &s_sg[wid][i0];
            if (i0 < L) {
                #pragma unroll 4
                for (int k = 1; k <= halfm; ++k) {
                    const float2 p  = base[k];
                    const float d   = me.x - p.x;
                    const float gd  = me.y - p.y;
                    const float nm  = fabsf(d) * (-LOG2E);
                    const float u   = ex2a(nm);            // MUFU.EX2
                    const float l   = lg2a(1.0f + u);      // MUFU.LG2
                    num = fmaf(-fabsf(gd), fmaf(2.0f, l, -nm), num);
                }
                // tie distance k=L/2 (L even), counted once by i0 < L/2 (no wrap)
                if (((L & 1) == 0) && (i0 < (L >> 1))) {
                    const float2 p  = base[L >> 1];
                    const float d   = me.x - p.x;
                    const float gd  = me.y - p.y;
                    const float nm  = fabsf(d) * (-LOG2E);
                    const float u   = ex2a(nm);
                    const float l   = lg2a(1.0f + u);
                    num = fmaf(-fabsf(gd), fmaf(2.0f, l, -nm), num);
                }
            }
        }

        // ---- ideal DCG via counting sort (gains in {0,1,3,7,15}) ----
        const int c4 = s_cnt[wid][4];
        const int c3 = c4 + s_cnt[wid][3];
        const int c2 = c3 + s_cnt[wid][2];
        const int c1 = c2 + s_cnt[wid][1];
        float idl = 0.0f;
        #pragma unroll
        for (int q = 0; q < 4; ++q) {
            const int r = lane + 32 * q;
            if (r < L) {
                float gr;
                if      (r < c4) gr = 15.0f;
                else if (r < c3) gr = 7.0f;
                else if (r < c2) gr = 3.0f;
                else if (r < c1) gr = 1.0f;
                else             gr = 0.0f;
                idl += __fdividef(gr, lg2a((float)(r + 2)));
            }
        }

        // ---- warp reduction ----
        #pragma unroll
        for (int off = 16; off > 0; off >>= 1) {
            num += __shfl_down_sync(0xFFFFFFFFu, num, off);
            idl += __shfl_down_sync(0xFFFFFFFFu, idl, off);
        }
        if (lane == 0) g_partials[row] = -num / (idl + EPS);
    }

    // ---- completion + fused deterministic final reduction ----
    __syncthreads();
    if (threadIdx.x == 0) {
        __threadfence();
        const unsigned int t = atomicAdd(&g_done, 1u);
        s_last = (t == (unsigned int)(gridDim.x - 1));
    }
    __syncthreads();

    if (s_last) {
        __threadfence();
        float s = 0.0f;
        for (int r = threadIdx.x; r < B; r += 128) s += g_partials[r];
        #pragma unroll
        for (int off = 16; off > 0; off >>= 1)
            s += __shfl_down_sync(0xFFFFFFFFu, s, off);
        if (lane == 0) s_red[wid] = s;
        __syncthreads();
        if (threadIdx.x == 0) {
            out[0] = (s_red[0] + s_red[1] + s_red[2] + s_red[3]) / (float)B;
            g_done = 0;   // reset for next graph replay
        }
    }
}

extern "C" void kernel_launch(void* const* d_in, const int* in_sizes, int n_in,
                              void* d_out, int out_size)
{
    const float* scores = (const float*)d_in[0];
    const int*   relev  = (const int*)  d_in[1];
    const int*   qlen   = (const int*)  d_in[2];
    float*       out    = (float*)      d_out;

    const int B = in_sizes[2];
    const int D = in_sizes[0] / B;   // 128

    const int blocks = (B + 3) / 4;
    ndcg_kernel<<<blocks, 128>>>(scores, relev, qlen, out, D, B);
}

// round 6
// speedup vs baseline: 1.4812x; 1.4812x over previous
#include <cuda_runtime.h>

#define LOG2E 1.4426950408889634f
#define EPS   1e-8f

__device__ float        g_partials[8192];
__device__ unsigned int g_done;   // zero-init; last block resets -> graph-replay safe

__device__ __forceinline__ float ex2a(float x) {
    float r; asm("ex2.approx.ftz.f32 %0, %1;" : "=f"(r) : "f"(x)); return r;
}
__device__ __forceinline__ float lg2a(float x) {
    float r; asm("lg2.approx.ftz.f32 %0, %1;" : "=f"(r) : "f"(x)); return r;
}

// Block-per-row, 128 threads. Row staged in smem as (score*log2e, gain) with
// the first 64 entries mirrored past L so partner index i+k never wraps.
__global__ void __launch_bounds__(128) ndcg_kernel(
    const float* __restrict__ scores,
    const int*   __restrict__ relev,
    const int*   __restrict__ qlen,
    float*       __restrict__ out,
    int D, int B)
{
    const int b = blockIdx.x;
    const int i = threadIdx.x;          // 0..127 = D

    __shared__ float2 s_sg[192];        // (s*log2e, gain), mirrored tail
    __shared__ int    s_cnt[8];
    __shared__ float  s_rnum[4];
    __shared__ float  s_ridl[4];
    __shared__ int    s_last;

    const int  L     = qlen[b];
    const bool valid = (i < L);

    const float sv = scores[b * D + i] * LOG2E;   // pre-scaled
    const int   rv = relev[b * D + i];
    const float gv = valid ? (float)((1 << rv) - 1) : 0.0f;   // 2^rel - 1

    s_sg[i] = make_float2(sv, gv);
    if (i < 8) s_cnt[i] = 0;
    __syncthreads();

    if (valid) atomicAdd(&s_cnt[rv], 1);
    // mirror first 64 docs past L (reads in loop reach at most L-1+63 <= 190)
    if (i < 64) s_sg[L + i] = s_sg[i];
    __syncthreads();

    // ---- pairwise sum over unordered valid pairs (cyclic-distance enum) ----
    // pair {i,j}, a=|s~i - s~j| (already in log2 units):
    //   contribution = -|gi-gj| * (a + 2*log2(1 + 2^{-a}))
    float num0 = 0.0f, num1 = 0.0f;
    if (valid && L > 1) {
        const int halfm = (L - 1) >> 1;
        const float2* base = &s_sg[i];
        const float   si   = sv;
        const float   gi   = gv;

        int k = 1;
        #pragma unroll 2
        for (; k + 1 <= halfm; k += 2) {
            const float2 p0 = base[k];
            const float2 p1 = base[k + 1];
            const float a0  = fabsf(si - p0.x);
            const float a1  = fabsf(si - p1.x);
            const float d0  = fabsf(gi - p0.y);
            const float d1  = fabsf(gi - p1.y);
            const float u0  = ex2a(-a0);
            const float u1  = ex2a(-a1);
            const float l0  = lg2a(1.0f + u0);
            const float l1  = lg2a(1.0f + u1);
            num0 = fmaf(-d0, fmaf(2.0f, l0, a0), num0);
            num1 = fmaf(-d1, fmaf(2.0f, l1, a1), num1);
        }
        if (k <= halfm) {
            const float2 p0 = base[k];
            const float a0  = fabsf(si - p0.x);
            const float d0  = fabsf(gi - p0.y);
            const float u0  = ex2a(-a0);
            const float l0  = lg2a(1.0f + u0);
            num0 = fmaf(-d0, fmaf(2.0f, l0, a0), num0);
        }
        // tie distance k=L/2 (L even): counted once by i < L/2 (no wrap needed)
        if (((L & 1) == 0) && (i < (L >> 1))) {
            const float2 p0 = s_sg[i + (L >> 1)];
            const float a0  = fabsf(si - p0.x);
            const float d0  = fabsf(gi - p0.y);
            const float u0  = ex2a(-a0);
            const float l0  = lg2a(1.0f + u0);
            num1 = fmaf(-d0, fmaf(2.0f, l0, a0), num1);
        }
    }
    float num = num0 + num1;

    // ---- ideal DCG via counting sort (gains in {0,1,3,7,15}) ----
    float idl = 0.0f;
    if (valid) {
        const int c4 = s_cnt[4];
        const int c3 = c4 + s_cnt[3];
        const int c2 = c3 + s_cnt[2];
        const int c1 = c2 + s_cnt[1];
        float gr;
        if      (i < c4) gr = 15.0f;
        else if (i < c3) gr = 7.0f;
        else if (i < c2) gr = 3.0f;
        else if (i < c1) gr = 1.0f;
        else             gr = 0.0f;
        idl = __fdividef(gr, lg2a((float)(i + 2)));
    }

    // ---- block reduction of (num, idl) ----
    #pragma unroll
    for (int off = 16; off > 0; off >>= 1) {
        num += __shfl_down_sync(0xFFFFFFFFu, num, off);
        idl += __shfl_down_sync(0xFFFFFFFFu, idl, off);
    }
    const int wid  = i >> 5;
    const int lane = i & 31;
    if (lane == 0) { s_rnum[wid] = num; s_ridl[wid] = idl; }
    __syncthreads();
    if (i == 0) {
        const float n  = s_rnum[0] + s_rnum[1] + s_rnum[2] + s_rnum[3];
        const float id = s_ridl[0] + s_ridl[1] + s_ridl[2] + s_ridl[3];
        g_partials[b] = -n / (id + EPS);
        __threadfence();
        const unsigned int t = atomicAdd(&g_done, 1u);
        s_last = (t == (unsigned int)(gridDim.x - 1));
    }
    __syncthreads();

    // ---- last block: deterministic final reduction ----
    if (s_last) {
        __threadfence();
        float s = 0.0f;
        for (int r = i; r < B; r += 128) s += g_partials[r];
        #pragma unroll
        for (int off = 16; off > 0; off >>= 1)
            s += __shfl_down_sync(0xFFFFFFFFu, s, off);
        if (lane == 0) s_rnum[wid] = s;
        __syncthreads();
        if (i == 0) {
            out[0] = (s_rnum[0] + s_rnum[1] + s_rnum[2] + s_rnum[3]) / (float)B;
            g_done = 0;   // reset for next graph replay
        }
    }
}

extern "C" void kernel_launch(void* const* d_in, const int* in_sizes, int n_in,
                              void* d_out, int out_size)
{
    const float* scores = (const float*)d_in[0];
    const int*   relev  = (const int*)  d_in[1];
    const int*   qlen   = (const int*)  d_in[2];
    float*       out    = (float*)      d_out;

    const int B = in_sizes[2];
    const int D = in_sizes[0] / B;   // 128

    ndcg_kernel<<<B, 128>>>(scores, relev, qlen, out, D, B);
}